// round 6
// baseline (speedup 1.0000x reference)
#include <cuda_runtime.h>
#include <math.h>

#define SL 512
#define BB 128
#define HH 1024
#define FT 576
#define MD 512
#define Z4 4096
#define NT (SL*BB)   // 65536 tokens
#define GCTA 148     // persistent grid size (<= SM count, all co-resident)

// ---------------- static device scratch (no cudaMalloc allowed) ----------------
static __device__ __align__(16) float g_X  [(size_t)NT*FT];  // embeddings [t*BB+b][FT]
static __device__ __align__(16) float g_pmx[(size_t)NT*HH];  // X@Wmx1^T
static __device__ __align__(16) float g_pih[(size_t)NT*Z4];  // X@Wih1^T + b1
static __device__ __align__(16) float g_d  [(size_t)NT];     // (X@Wsi^T+b_bd)·vs per token
static __device__ __align__(16) float g_w  [FT];             // Wsi^T vs
static __device__ __align__(16) float g_u  [HH];             // Wsh^T vs
static __device__ float g_c0[1];                             // b_bd·vs
static __device__ __align__(16) float g_h1[BB*HH], g_c1[BB*HH], g_h2[BB*HH], g_c2[BB*HH];
static __device__ __align__(16) float g_m1[BB*HH], g_x2[BB*HH], g_m2[BB*HH], g_t2[BB*HH];
static __device__ __align__(16) float g_z1[BB*Z4], g_z2[BB*Z4];
static __device__ float g_s[BB];
static __device__ float g_flagbuf[2];

// grid barrier state
static __device__ unsigned g_bar_count = 0;
static __device__ volatile unsigned g_bar_gen = 0;

__device__ __forceinline__ float sigf(float x) { return 1.0f / (1.0f + expf(-x)); }

__device__ __forceinline__ void gsync(unsigned nb)
{
    __syncthreads();
    if (threadIdx.x == 0) {
        __threadfence();                       // release (CCTL.IVALL at gpu scope)
        unsigned gen = g_bar_gen;
        if (atomicAdd(&g_bar_count, 1u) == nb - 1u) {
            g_bar_count = 0;
            __threadfence();
            g_bar_gen = gen + 1u;
        } else {
            while (g_bar_gen == gen) __nanosleep(64);
        }
        __threadfence();                       // acquire: flush L1 so stale lines drop
    }
    __syncthreads();
}

// ---------------- prep: w = Wsi^T vs, u = Wsh^T vs, c0 = b_bd·vs ----------------
__global__ void k_prep(const float* __restrict__ vs, const float* __restrict__ Wsi,
                       const float* __restrict__ Wsh, const float* __restrict__ b_bd)
{
    int i = blockIdx.x;
    __shared__ float red[256];
    float acc = 0.f;
    if (i < FT) {
        for (int j = threadIdx.x; j < MD; j += 256) acc += vs[j] * Wsi[(size_t)j*FT + i];
    } else if (i < FT + HH) {
        int h = i - FT;
        for (int j = threadIdx.x; j < MD; j += 256) acc += vs[j] * Wsh[(size_t)j*HH + h];
    } else {
        for (int j = threadIdx.x; j < MD; j += 256) acc += vs[j] * b_bd[j];
    }
    red[threadIdx.x] = acc; __syncthreads();
    for (int off = 128; off; off >>= 1) {
        if (threadIdx.x < off) red[threadIdx.x] += red[threadIdx.x + off];
        __syncthreads();
    }
    if (threadIdx.x == 0) {
        if (i < FT) g_w[i] = red[0];
        else if (i < FT + HH) g_u[i - FT] = red[0];
        else g_c0[0] = red[0];
    }
}

// ---------------- embedding gather + fused boundary GEMV ----------------
__global__ void k_embed(const int* __restrict__ enc, const int* __restrict__ encx,
                        const float* __restrict__ wemb, const float* __restrict__ xemb)
{
    int n = blockIdx.x;          // token index, time-major
    int t = n >> 7;
    int b = n & 127;
    int w = enc [b*SL + t];
    int e = encx[b*SL + t];
    float4* dst = (float4*)(g_X + (size_t)n*FT);
    const float4* ws = (const float4*)(wemb + (size_t)w*512);
    const float4* xs = (const float4*)(xemb + (size_t)e*64);
    const float4* w4 = (const float4*)g_w;
    float dot = 0.f;
    for (int i = threadIdx.x; i < 128; i += 128) {
        float4 v = ws[i]; dst[i] = v;
        float4 c = w4[i];
        dot += v.x*c.x + v.y*c.y + v.z*c.z + v.w*c.w;
    }
    for (int i = threadIdx.x; i < 16; i += 128) {
        float4 v = xs[i]; dst[128 + i] = v;
        float4 c = w4[128 + i];
        dot += v.x*c.x + v.y*c.y + v.z*c.z + v.w*c.w;
    }
    __shared__ float red[128];
    red[threadIdx.x] = dot; __syncthreads();
    for (int off = 64; off; off >>= 1) {
        if (threadIdx.x < off) red[threadIdx.x] += red[threadIdx.x + off];
        __syncthreads();
    }
    if (threadIdx.x == 0) g_d[n] = red[0] + g_c0[0];
}

// ---------------- precompute GEMM (global kernel): C = epi(A @ W^T) ----------------
// EPI: 0 none, 1 +bias[n]
template<int EPI>
__global__ void __launch_bounds__(256, 1) gemm64k(
    const float* __restrict__ A, const float* __restrict__ W,
    float* __restrict__ C, int N, int K, const float* __restrict__ ex)
{
    __shared__ __align__(16) float As[16*68];
    __shared__ __align__(16) float Ws[16*68];
    const int tid  = threadIdx.x;
    const int row0 = blockIdx.y * 64;
    const int col0 = blockIdx.x * 64;
    const int lm = tid >> 2;
    const int lq = (tid & 3) * 4;
    const float* Ag = A + (size_t)(row0 + lm) * K + lq;
    const float* Wg = W + (size_t)(col0 + lm) * K + lq;
    const int m0 = (tid >> 4) * 4;
    const int n0 = (tid & 15) * 4;
    float acc[4][4] = {};
    float4 av = *(const float4*)Ag;
    float4 wv = *(const float4*)Wg;
    for (int kt = 0; kt < K; kt += 16) {
        __syncthreads();
        As[(lq+0)*68 + lm] = av.x;  As[(lq+1)*68 + lm] = av.y;
        As[(lq+2)*68 + lm] = av.z;  As[(lq+3)*68 + lm] = av.w;
        Ws[(lq+0)*68 + lm] = wv.x;  Ws[(lq+1)*68 + lm] = wv.y;
        Ws[(lq+2)*68 + lm] = wv.z;  Ws[(lq+3)*68 + lm] = wv.w;
        __syncthreads();
        if (kt + 16 < K) {
            av = *(const float4*)(Ag + kt + 16);
            wv = *(const float4*)(Wg + kt + 16);
        }
        #pragma unroll
        for (int kk = 0; kk < 16; kk++) {
            float4 a = *(const float4*)(As + kk*68 + m0);
            float4 w = *(const float4*)(Ws + kk*68 + n0);
            acc[0][0]+=a.x*w.x; acc[0][1]+=a.x*w.y; acc[0][2]+=a.x*w.z; acc[0][3]+=a.x*w.w;
            acc[1][0]+=a.y*w.x; acc[1][1]+=a.y*w.y; acc[1][2]+=a.y*w.z; acc[1][3]+=a.y*w.w;
            acc[2][0]+=a.z*w.x; acc[2][1]+=a.z*w.y; acc[2][2]+=a.z*w.z; acc[2][3]+=a.z*w.w;
            acc[3][0]+=a.w*w.x; acc[3][1]+=a.w*w.y; acc[3][2]+=a.w*w.z; acc[3][3]+=a.w*w.w;
        }
    }
    #pragma unroll
    for (int i = 0; i < 4; i++) {
        size_t ci = (size_t)(row0 + m0 + i) * N + col0 + n0;
        float4 r = make_float4(acc[i][0], acc[i][1], acc[i][2], acc[i][3]);
        if (EPI == 1) {
            r.x += ex[col0+n0+0]; r.y += ex[col0+n0+1];
            r.z += ex[col0+n0+2]; r.w += ex[col0+n0+3];
        }
        *(float4*)(C + ci) = r;
    }
}

// ---------------- device GEMM tiles for the persistent kernel ----------------
// EPI: 0 none, 1 +bias[n], 2 +ex[full], 3 *ex[full]
template<int EPI>
__device__ __forceinline__ void dgemm64(
    const float* __restrict__ A, const float* __restrict__ W,
    float* __restrict__ C, int N, int K, const float* __restrict__ ex,
    int row0, int col0, float* As, float* Ws)
{
    const int tid = threadIdx.x;
    const int lm = tid >> 2;
    const int lq = (tid & 3) * 4;
    const float* Ag = A + (size_t)(row0 + lm) * K + lq;
    const float* Wg = W + (size_t)(col0 + lm) * K + lq;
    const int m0 = (tid >> 4) * 4;
    const int n0 = (tid & 15) * 4;
    float acc[4][4] = {};
    float4 av = *(const float4*)Ag;
    float4 wv = *(const float4*)Wg;
    for (int kt = 0; kt < K; kt += 16) {
        __syncthreads();
        As[(lq+0)*68 + lm] = av.x;  As[(lq+1)*68 + lm] = av.y;
        As[(lq+2)*68 + lm] = av.z;  As[(lq+3)*68 + lm] = av.w;
        Ws[(lq+0)*68 + lm] = wv.x;  Ws[(lq+1)*68 + lm] = wv.y;
        Ws[(lq+2)*68 + lm] = wv.z;  Ws[(lq+3)*68 + lm] = wv.w;
        __syncthreads();
        if (kt + 16 < K) {
            av = *(const float4*)(Ag + kt + 16);
            wv = *(const float4*)(Wg + kt + 16);
        }
        #pragma unroll
        for (int kk = 0; kk < 16; kk++) {
            float4 a = *(const float4*)(As + kk*68 + m0);
            float4 w = *(const float4*)(Ws + kk*68 + n0);
            acc[0][0]+=a.x*w.x; acc[0][1]+=a.x*w.y; acc[0][2]+=a.x*w.z; acc[0][3]+=a.x*w.w;
            acc[1][0]+=a.y*w.x; acc[1][1]+=a.y*w.y; acc[1][2]+=a.y*w.z; acc[1][3]+=a.y*w.w;
            acc[2][0]+=a.z*w.x; acc[2][1]+=a.z*w.y; acc[2][2]+=a.z*w.z; acc[2][3]+=a.z*w.w;
            acc[3][0]+=a.w*w.x; acc[3][1]+=a.w*w.y; acc[3][2]+=a.w*w.z; acc[3][3]+=a.w*w.w;
        }
    }
    #pragma unroll
    for (int i = 0; i < 4; i++) {
        size_t ci = (size_t)(row0 + m0 + i) * N + col0 + n0;
        float4 r = make_float4(acc[i][0], acc[i][1], acc[i][2], acc[i][3]);
        if (EPI == 1) {
            r.x += ex[col0+n0+0]; r.y += ex[col0+n0+1];
            r.z += ex[col0+n0+2]; r.w += ex[col0+n0+3];
        } else if (EPI == 2) {
            float4 e = *(const float4*)(ex + ci);
            r.x += e.x; r.y += e.y; r.z += e.z; r.w += e.w;
        } else if (EPI == 3) {
            float4 e = *(const float4*)(ex + ci);
            r.x *= e.x; r.y *= e.y; r.z *= e.z; r.w *= e.w;
        }
        *(float4*)(C + ci) = r;
    }
}

template<int EPI>
__device__ __forceinline__ void dgemm32(
    const float* __restrict__ A, const float* __restrict__ W,
    float* __restrict__ C, int N, int K, const float* __restrict__ ex,
    int row0, int col0, float* As, float* Ws)
{
    const int tid = threadIdx.x;
    const int half = tid >> 7;
    const int li = tid & 127;
    const int lm = li >> 2;
    const int lq = (li & 3) * 4;
    const float* G = half ? (W + (size_t)(col0 + lm)*K + lq)
                          : (A + (size_t)(row0 + lm)*K + lq);
    float* Sm = half ? Ws : As;
    const int m0 = (tid >> 4) * 2;
    const int n0 = (tid & 15) * 2;
    float acc[2][2] = {};
    float4 v = *(const float4*)G;
    for (int kt = 0; kt < K; kt += 16) {
        __syncthreads();
        Sm[(lq+0)*36 + lm] = v.x;  Sm[(lq+1)*36 + lm] = v.y;
        Sm[(lq+2)*36 + lm] = v.z;  Sm[(lq+3)*36 + lm] = v.w;
        __syncthreads();
        if (kt + 16 < K) v = *(const float4*)(G + kt + 16);
        #pragma unroll
        for (int kk = 0; kk < 16; kk++) {
            float2 a = *(const float2*)(As + kk*36 + m0);
            float2 w = *(const float2*)(Ws + kk*36 + n0);
            acc[0][0]+=a.x*w.x; acc[0][1]+=a.x*w.y;
            acc[1][0]+=a.y*w.x; acc[1][1]+=a.y*w.y;
        }
    }
    #pragma unroll
    for (int i = 0; i < 2; i++) {
        size_t ci = (size_t)(row0 + m0 + i) * N + col0 + n0;
        float2 r = make_float2(acc[i][0], acc[i][1]);
        if (EPI == 2) { float2 e = *(const float2*)(ex + ci); r.x += e.x; r.y += e.y; }
        else if (EPI == 3) { float2 e = *(const float2*)(ex + ci); r.x *= e.x; r.y *= e.y; }
        *(float2*)(C + ci) = r;
    }
}

// ---------------- per-item elementwise pieces ----------------
__device__ __forceinline__ void gate1_item(int g)
{
    int b0 = g*8;
    for (int b = b0; b < b0+8; b++) {
        float s = g_s[b];
        size_t zb = (size_t)b*Z4;
        int base = b*HH;
        for (int h = threadIdx.x; h < HH; h += 256) {
            float zi = g_z1[zb+h],      zf = g_z1[zb+HH+h];
            float zg = g_z1[zb+2*HH+h], zo = g_z1[zb+3*HH+h];
            float c  = sigf(zf)*g_c1[base+h] + sigf(zi)*tanhf(zg);
            float hv = sigf(zo)*tanhf(c);
            g_x2[base+h] = hv * s;
            g_h1[base+h] = hv * (1.f - s);
            g_c1[base+h] = c  * (1.f - s);
        }
    }
}

__device__ __forceinline__ void gate2out_item(int t, int g, float* __restrict__ out, bool fin)
{
    bool upd = g_flagbuf[t & 1] > 0.5f;
    int b0 = g*8;
    for (int b = b0; b < b0+8; b++) {
        size_t zb = (size_t)b*Z4;
        int base = b*HH;
        for (int h = threadIdx.x; h < HH; h += 256) {
            float hv, cv;
            if (upd) {
                float zi = g_z2[zb+h],      zf = g_z2[zb+HH+h];
                float zg = g_z2[zb+2*HH+h], zo = g_z2[zb+3*HH+h];
                cv = sigf(zf)*g_c2[base+h] + sigf(zi)*tanhf(zg);
                hv = sigf(zo)*tanhf(cv);
                g_c2[base+h] = cv; g_h2[base+h] = hv;
            } else {
                hv = g_h2[base+h]; cv = g_c2[base+h];
            }
            out[(size_t)b*SL*HH + (size_t)t*HH + h] = hv;
            if (fin) {
                size_t off = (size_t)BB*SL*HH;
                out[off + base + h]                   = hv;
                out[off + (size_t)BB*HH + base + h]   = cv;
            }
        }
    }
}

__device__ __forceinline__ void sdot_item(int t, int k, float* __restrict__ out)
{
    int warp = threadIdx.x >> 5, lane = threadIdx.x & 31;
    int base = k*32 + warp*4;
    for (int bi = 0; bi < 4; bi++) {
        int b = base + bi;
        const float* hp = g_h1 + (size_t)b*HH;
        float p = 0.f;
        for (int j = lane; j < HH; j += 32) p += hp[j] * g_u[j];
        #pragma unroll
        for (int o = 16; o; o >>= 1) p += __shfl_xor_sync(0xffffffffu, p, o);
        if (lane == 0) {
            float sv = (p + g_d[(size_t)t*BB + b] > 0.f) ? 1.f : 0.f;
            g_s[b] = sv;
            if (b == 0) {
                g_flagbuf[t & 1] = sv;
                out[(size_t)BB*SL*HH + 2*(size_t)BB*HH + t] = sv;  // flags[t]
            }
        }
    }
}

// ---------------- persistent recurrent-loop kernel ----------------
__global__ void __launch_bounds__(256, 1) k_loop(
    const float* __restrict__ Wmh1, const float* __restrict__ Whh1,
    const float* __restrict__ Wmx2, const float* __restrict__ Wmh2,
    const float* __restrict__ Wih2, const float* __restrict__ Whh2,
    const float* __restrict__ b2, float* __restrict__ out)
{
    __shared__ __align__(16) float sm[2*16*68];
    float* As = sm;
    float* Ws = sm + 16*68;
    const int bid = blockIdx.x;
    const unsigned G = gridDim.x;

    for (int t = 0; t < SL; t++) {
        const float* pre_mx = g_pmx + (size_t)t*BB*HH;
        const float* pre_ih = g_pih + (size_t)t*BB*Z4;

        // Phase A: m1 = pre_mx*(h1@Wmh1^T)  |  gate2+out for step t-1  |  s(t) dots
        for (int it = bid; it < 148; it += G) {
            if (it < 128)
                dgemm32<3>(g_h1, Wmh1, g_m1, HH, HH, pre_mx, (it>>5)*32, (it&31)*32, As, Ws);
            else if (it < 144) {
                if (t > 0) gate2out_item(t-1, it-128, out, false);
            } else
                sdot_item(t, it-144, out);
        }
        gsync(G);

        // Phase B: z1 = pre_ih + m1@Whh1^T
        for (int it = bid; it < 128; it += G)
            dgemm64<2>(g_m1, Whh1, g_z1, Z4, HH, pre_ih, (it>>6)*64, (it&63)*64, As, Ws);
        gsync(G);

        float flag = g_flagbuf[t & 1];

        // Phase C: gate1 (x2, h1*=1-s, c1*=1-s)  |  t2 = h2@Wmh2^T (if flag)
        for (int it = bid; it < 144; it += G) {
            if (it < 128) {
                if (flag > 0.5f)
                    dgemm32<0>(g_h2, Wmh2, g_t2, HH, HH, nullptr, (it>>5)*32, (it&31)*32, As, Ws);
            } else
                gate1_item(it - 128);
        }
        gsync(G);

        if (flag > 0.5f) {
            // Phase D: z2 = x2@Wih2^T + b2  |  m2 = (x2@Wmx2^T)*t2
            for (int it = bid; it < 256; it += G) {
                if (it < 128)
                    dgemm64<1>(g_x2, Wih2, g_z2, Z4, HH, b2, (it>>6)*64, (it&63)*64, As, Ws);
                else {
                    int j = it - 128;
                    dgemm32<3>(g_x2, Wmx2, g_m2, HH, HH, g_t2, (j>>5)*32, (j&31)*32, As, Ws);
                }
            }
            gsync(G);
            // Phase E: z2 += m2@Whh2^T (in place)
            for (int it = bid; it < 128; it += G)
                dgemm64<2>(g_m2, Whh2, g_z2, Z4, HH, g_z2, (it>>6)*64, (it&63)*64, As, Ws);
            gsync(G);
        }
    }

    // final step output + final states (h2f, c2f)
    for (int it = bid; it < 16; it += (int)G)
        gate2out_item(SL-1, it, out, true);
}

// ---------------- host ----------------
extern "C" void kernel_launch(void* const* d_in, const int* in_sizes, int n_in,
                              void* d_out, int out_size)
{
    const int*   enc  = (const int*)  d_in[0];
    const int*   encx = (const int*)  d_in[1];
    const float* wemb = (const float*)d_in[2];
    const float* xemb = (const float*)d_in[3];
    const float* Wsi  = (const float*)d_in[4];
    const float* Wsh  = (const float*)d_in[5];
    const float* b_bd = (const float*)d_in[6];
    const float* vs   = (const float*)d_in[7];
    const float* Wmx1 = (const float*)d_in[8];
    const float* Wmh1 = (const float*)d_in[9];
    const float* Wih1 = (const float*)d_in[10];
    const float* Whh1 = (const float*)d_in[11];
    const float* b1   = (const float*)d_in[12];
    const float* Wmx2 = (const float*)d_in[13];
    const float* Wmh2 = (const float*)d_in[14];
    const float* Wih2 = (const float*)d_in[15];
    const float* Whh2 = (const float*)d_in[16];
    const float* b2   = (const float*)d_in[17];
    float* out = (float*)d_out;

    float *pX, *pmx, *pih, *ph1, *pc1, *ph2, *pc2;
    cudaGetSymbolAddress((void**)&pX,  g_X);
    cudaGetSymbolAddress((void**)&pmx, g_pmx);
    cudaGetSymbolAddress((void**)&pih, g_pih);
    cudaGetSymbolAddress((void**)&ph1, g_h1);
    cudaGetSymbolAddress((void**)&pc1, g_c1);
    cudaGetSymbolAddress((void**)&ph2, g_h2);
    cudaGetSymbolAddress((void**)&pc2, g_c2);

    // zero initial states
    cudaMemsetAsync(ph1, 0, (size_t)BB*HH*sizeof(float));
    cudaMemsetAsync(pc1, 0, (size_t)BB*HH*sizeof(float));
    cudaMemsetAsync(ph2, 0, (size_t)BB*HH*sizeof(float));
    cudaMemsetAsync(pc2, 0, (size_t)BB*HH*sizeof(float));

    // precompute: boundary projections, embeddings (+fused GEMV), x-GEMMs
    k_prep<<<FT + HH + 1, 256>>>(vs, Wsi, Wsh, b_bd);
    k_embed<<<NT, 128>>>(enc, encx, wemb, xemb);
    gemm64k<0><<<dim3(HH/64, NT/64), 256>>>(pX, Wmx1, pmx, HH, FT, nullptr); // X@Wmx1^T
    gemm64k<1><<<dim3(Z4/64, NT/64), 256>>>(pX, Wih1, pih, Z4, FT, b1);      // X@Wih1^T + b1

    // entire recurrent loop in ONE persistent kernel (grid-sync inside)
    k_loop<<<GCTA, 256>>>(Wmh1, Whh1, Wmx2, Wmh2, Wih2, Whh2, b2, out);
}

// round 7
// speedup vs baseline: 1.2135x; 1.2135x over previous
#include <cuda_runtime.h>
#include <math.h>

#define SL 512
#define BB 128
#define HH 1024
#define FT 576
#define MD 512
#define Z4 4096
#define NT (SL*BB)   // 65536 tokens
#define GCTA 148

typedef unsigned long long u64t;

// ---------------- static device scratch ----------------
static __device__ __align__(16) float g_X  [(size_t)NT*FT];
static __device__ __align__(16) float g_pmx[(size_t)NT*HH];   // X@Wmx1^T
static __device__ __align__(16) float g_pih[(size_t)NT*Z4];   // X@Wih1^T + b1
static __device__ __align__(16) float g_d  [(size_t)NT];      // (X@Wsi^T+b_bd)·vs
static __device__ __align__(16) float g_w  [FT];              // Wsi^T vs
static __device__ __align__(16) float g_u  [HH];              // Wsh^T vs
static __device__ float g_c0[1];
static __device__ __align__(16) float g_h1[BB*HH], g_c1[BB*HH], g_h2[BB*HH], g_c2[BB*HH];
static __device__ __align__(16) float g_m1[BB*HH], g_x2[BB*HH], g_m2[BB*HH];
// K-split partial buffers
static __device__ __align__(16) float g_m1P [16*(size_t)BB*HH];
static __device__ __align__(16) float g_t2P [16*(size_t)BB*HH];
static __device__ __align__(16) float g_m2xP[16*(size_t)BB*HH];
static __device__ __align__(16) float g_z1P [8*(size_t)BB*Z4];
static __device__ __align__(16) float g_z2aP[8*(size_t)BB*Z4];
static __device__ __align__(16) float g_z2bP[8*(size_t)BB*Z4];
static __device__ float g_s[BB];
static __device__ float g_flagbuf[2];

static __device__ unsigned g_bar_count = 0;
static __device__ volatile unsigned g_bar_gen = 0;

__device__ __forceinline__ float sigf(float x) { return 1.0f / (1.0f + expf(-x)); }

__device__ __forceinline__ u64t pk2(float lo, float hi) {
    u64t r; asm("mov.b64 %0, {%1, %2};" : "=l"(r) : "f"(lo), "f"(hi)); return r;
}
__device__ __forceinline__ u64t dup2(float v) {
    u64t r; asm("mov.b64 %0, {%1, %1};" : "=l"(r) : "f"(v)); return r;
}
__device__ __forceinline__ void fma2(u64t& d, u64t a, u64t b) {
    asm("fma.rn.f32x2 %0, %1, %2, %0;" : "+l"(d) : "l"(a), "l"(b));
}
__device__ __forceinline__ void upk2(u64t v, float& lo, float& hi) {
    asm("mov.b64 {%0, %1}, %2;" : "=f"(lo), "=f"(hi) : "l"(v));
}

__device__ __forceinline__ void gsync(unsigned nb)
{
    __syncthreads();
    if (threadIdx.x == 0) {
        __threadfence();
        unsigned gen = g_bar_gen;
        if (atomicAdd(&g_bar_count, 1u) == nb - 1u) {
            g_bar_count = 0;
            __threadfence();
            g_bar_gen = gen + 1u;
        } else {
            while (g_bar_gen == gen) __nanosleep(64);
        }
        __threadfence();
    }
    __syncthreads();
}

// ================= core fp32x2 GEMM tile: C[128x128] = A[128xK] @ W^T =================
// EPI: 0 plain, 1 +bias[col], 2 +ex[C-indexed]
template<int EPI>
__device__ __noinline__ void dg128(
    const float* __restrict__ A, int lda,
    const float* __restrict__ W, int ldw,
    float* __restrict__ C, int ldc,
    int row0, int col0, int k0, int niter,
    const float* __restrict__ ex,
    float* __restrict__ As, float* __restrict__ Ws)
{
    const int tid = threadIdx.x;
    const int lm = tid >> 1;
    const int kq = (tid & 1) << 3;
    const float* Ag = A + (size_t)(row0 + lm)*lda + k0 + kq;
    const float* Wg = W + (size_t)(col0 + lm)*ldw + k0 + kq;
    const int m0 = (tid >> 4) << 3;
    const int n0 = (tid & 15) << 3;
    u64t acc[4][8];
    #pragma unroll
    for (int i = 0; i < 4; i++)
        #pragma unroll
        for (int j = 0; j < 8; j++) acc[i][j] = 0ull;

    float4 a0 = *(const float4*)Ag;
    float4 a1 = *(const float4*)(Ag + 4);
    float4 w0 = *(const float4*)Wg;
    float4 w1 = *(const float4*)(Wg + 4);

    for (int it = 0; it < niter; it++) {
        __syncthreads();
        As[(kq+0)*132+lm]=a0.x; As[(kq+1)*132+lm]=a0.y; As[(kq+2)*132+lm]=a0.z; As[(kq+3)*132+lm]=a0.w;
        As[(kq+4)*132+lm]=a1.x; As[(kq+5)*132+lm]=a1.y; As[(kq+6)*132+lm]=a1.z; As[(kq+7)*132+lm]=a1.w;
        Ws[(kq+0)*132+lm]=w0.x; Ws[(kq+1)*132+lm]=w0.y; Ws[(kq+2)*132+lm]=w0.z; Ws[(kq+3)*132+lm]=w0.w;
        Ws[(kq+4)*132+lm]=w1.x; Ws[(kq+5)*132+lm]=w1.y; Ws[(kq+6)*132+lm]=w1.z; Ws[(kq+7)*132+lm]=w1.w;
        __syncthreads();
        if (it + 1 < niter) {
            const float* An = Ag + (it+1)*16;
            const float* Wn = Wg + (it+1)*16;
            a0 = *(const float4*)An; a1 = *(const float4*)(An + 4);
            w0 = *(const float4*)Wn; w1 = *(const float4*)(Wn + 4);
        }
        #pragma unroll
        for (int kk = 0; kk < 16; kk++) {
            const float* ar = As + kk*132;
            const float* wr = Ws + kk*132;
            float4 xa0 = *(const float4*)(ar + m0);
            float4 xa1 = *(const float4*)(ar + m0 + 4);
            float4 xw0 = *(const float4*)(wr + n0);
            float4 xw1 = *(const float4*)(wr + n0 + 4);
            u64t pa[4] = { pk2(xa0.x,xa0.y), pk2(xa0.z,xa0.w),
                           pk2(xa1.x,xa1.y), pk2(xa1.z,xa1.w) };
            u64t dw[8] = { dup2(xw0.x), dup2(xw0.y), dup2(xw0.z), dup2(xw0.w),
                           dup2(xw1.x), dup2(xw1.y), dup2(xw1.z), dup2(xw1.w) };
            #pragma unroll
            for (int i = 0; i < 4; i++)
                #pragma unroll
                for (int j = 0; j < 8; j++) fma2(acc[i][j], pa[i], dw[j]);
        }
    }

    #pragma unroll
    for (int i = 0; i < 4; i++) {
        float lo[8], hi[8];
        #pragma unroll
        for (int j = 0; j < 8; j++) upk2(acc[i][j], lo[j], hi[j]);
        size_t r0 = (size_t)(row0 + m0 + 2*i) * ldc + col0 + n0;
        size_t r1 = r0 + ldc;
        float4 v0 = make_float4(lo[0],lo[1],lo[2],lo[3]);
        float4 v1 = make_float4(lo[4],lo[5],lo[6],lo[7]);
        float4 u0 = make_float4(hi[0],hi[1],hi[2],hi[3]);
        float4 u1 = make_float4(hi[4],hi[5],hi[6],hi[7]);
        if (EPI == 1) {
            float4 b0 = *(const float4*)(ex + col0 + n0);
            float4 b1 = *(const float4*)(ex + col0 + n0 + 4);
            v0.x+=b0.x; v0.y+=b0.y; v0.z+=b0.z; v0.w+=b0.w;
            v1.x+=b1.x; v1.y+=b1.y; v1.z+=b1.z; v1.w+=b1.w;
            u0.x+=b0.x; u0.y+=b0.y; u0.z+=b0.z; u0.w+=b0.w;
            u1.x+=b1.x; u1.y+=b1.y; u1.z+=b1.z; u1.w+=b1.w;
        } else if (EPI == 2) {
            float4 e0 = *(const float4*)(ex + r0);
            float4 e1 = *(const float4*)(ex + r0 + 4);
            float4 e2 = *(const float4*)(ex + r1);
            float4 e3 = *(const float4*)(ex + r1 + 4);
            v0.x+=e0.x; v0.y+=e0.y; v0.z+=e0.z; v0.w+=e0.w;
            v1.x+=e1.x; v1.y+=e1.y; v1.z+=e1.z; v1.w+=e1.w;
            u0.x+=e2.x; u0.y+=e2.y; u0.z+=e2.z; u0.w+=e2.w;
            u1.x+=e3.x; u1.y+=e3.y; u1.z+=e3.z; u1.w+=e3.w;
        }
        *(float4*)(C + r0)     = v0;
        *(float4*)(C + r0 + 4) = v1;
        *(float4*)(C + r1)     = u0;
        *(float4*)(C + r1 + 4) = u1;
    }
}

// ---------------- precompute GEMM wrapper ----------------
template<int EPI>
__global__ void __launch_bounds__(256, 1) gemmP(
    const float* __restrict__ A, int lda, const float* __restrict__ W,
    float* __restrict__ C, int N, int K, const float* __restrict__ bias)
{
    __shared__ __align__(16) float As[16*132];
    __shared__ __align__(16) float Ws[16*132];
    dg128<EPI>(A, lda, W, K, C, N, blockIdx.y*128, blockIdx.x*128, 0, K/16, bias, As, Ws);
}

// ---------------- prep: w = Wsi^T vs, u = Wsh^T vs, c0 = b_bd·vs ----------------
__global__ void k_prep(const float* __restrict__ vs, const float* __restrict__ Wsi,
                       const float* __restrict__ Wsh, const float* __restrict__ b_bd)
{
    int i = blockIdx.x;
    __shared__ float red[256];
    float acc = 0.f;
    if (i < FT) {
        for (int j = threadIdx.x; j < MD; j += 256) acc += vs[j] * Wsi[(size_t)j*FT + i];
    } else if (i < FT + HH) {
        int h = i - FT;
        for (int j = threadIdx.x; j < MD; j += 256) acc += vs[j] * Wsh[(size_t)j*HH + h];
    } else {
        for (int j = threadIdx.x; j < MD; j += 256) acc += vs[j] * b_bd[j];
    }
    red[threadIdx.x] = acc; __syncthreads();
    for (int off = 128; off; off >>= 1) {
        if (threadIdx.x < off) red[threadIdx.x] += red[threadIdx.x + off];
        __syncthreads();
    }
    if (threadIdx.x == 0) {
        if (i < FT) g_w[i] = red[0];
        else if (i < FT + HH) g_u[i - FT] = red[0];
        else g_c0[0] = red[0];
    }
}

// ---------------- embedding gather + fused boundary GEMV ----------------
__global__ void k_embed(const int* __restrict__ enc, const int* __restrict__ encx,
                        const float* __restrict__ wemb, const float* __restrict__ xemb)
{
    int n = blockIdx.x;
    int t = n >> 7;
    int b = n & 127;
    int w = enc [b*SL + t];
    int e = encx[b*SL + t];
    float4* dst = (float4*)(g_X + (size_t)n*FT);
    const float4* ws = (const float4*)(wemb + (size_t)w*512);
    const float4* xs = (const float4*)(xemb + (size_t)e*64);
    const float4* w4 = (const float4*)g_w;
    float dot = 0.f;
    for (int i = threadIdx.x; i < 128; i += 128) {
        float4 v = ws[i]; dst[i] = v;
        float4 c = w4[i];
        dot += v.x*c.x + v.y*c.y + v.z*c.z + v.w*c.w;
    }
    for (int i = threadIdx.x; i < 16; i += 128) {
        float4 v = xs[i]; dst[128 + i] = v;
        float4 c = w4[128 + i];
        dot += v.x*c.x + v.y*c.y + v.z*c.z + v.w*c.w;
    }
    __shared__ float red[128];
    red[threadIdx.x] = dot; __syncthreads();
    for (int off = 64; off; off >>= 1) {
        if (threadIdx.x < off) red[threadIdx.x] += red[threadIdx.x + off];
        __syncthreads();
    }
    if (threadIdx.x == 0) g_d[n] = red[0] + g_c0[0];
}

// ---------------- per-item elementwise pieces (persistent kernel) ----------------
__device__ __forceinline__ float4 f4add(float4 a, float4 b) {
    return make_float4(a.x+b.x, a.y+b.y, a.z+b.z, a.w+b.w);
}

__device__ void fin_m1(int g, const float* __restrict__ pre_mx)
{
    const float4* P = (const float4*)g_m1P;
    const float4* M = (const float4*)pre_mx;
    float4* O = (float4*)g_m1;
    for (int i = threadIdx.x; i < 2048; i += 256) {
        int idx = g*2048 + i;
        float4 s = make_float4(0.f,0.f,0.f,0.f);
        #pragma unroll
        for (int c = 0; c < 16; c++) s = f4add(s, P[(size_t)c*32768 + idx]);
        float4 m = M[idx];
        O[idx] = make_float4(s.x*m.x, s.y*m.y, s.z*m.z, s.w*m.w);
    }
}

__device__ void fin_m2(int g)
{
    const float4* P = (const float4*)g_m2xP;
    const float4* T = (const float4*)g_t2P;
    float4* O = (float4*)g_m2;
    for (int i = threadIdx.x; i < 2048; i += 256) {
        int idx = g*2048 + i;
        float4 s = make_float4(0.f,0.f,0.f,0.f);
        float4 u = make_float4(0.f,0.f,0.f,0.f);
        #pragma unroll
        for (int c = 0; c < 16; c++) {
            s = f4add(s, P[(size_t)c*32768 + idx]);
            u = f4add(u, T[(size_t)c*32768 + idx]);
        }
        O[idx] = make_float4(s.x*u.x, s.y*u.y, s.z*u.z, s.w*u.w);
    }
}

__device__ void gate1_item(int g, const float* __restrict__ pre_ih)
{
    int b0 = g*8;
    int h = threadIdx.x * 4;
    for (int b = b0; b < b0+8; b++) {
        float s = g_s[b];
        const float* pz = pre_ih + (size_t)b*Z4;
        float4 zi = *(const float4*)(pz + h);
        float4 zf = *(const float4*)(pz + HH + h);
        float4 zg = *(const float4*)(pz + 2*HH + h);
        float4 zo = *(const float4*)(pz + 3*HH + h);
        #pragma unroll
        for (int c = 0; c < 8; c++) {
            const float* pp = g_z1P + (size_t)c*BB*Z4 + (size_t)b*Z4;
            zi = f4add(zi, *(const float4*)(pp + h));
            zf = f4add(zf, *(const float4*)(pp + HH + h));
            zg = f4add(zg, *(const float4*)(pp + 2*HH + h));
            zo = f4add(zo, *(const float4*)(pp + 3*HH + h));
        }
        int base = b*HH + h;
        float4 c1 = *(const float4*)(g_c1 + base);
        float4 cn, hn;
        cn.x = sigf(zf.x)*c1.x + sigf(zi.x)*tanhf(zg.x);
        cn.y = sigf(zf.y)*c1.y + sigf(zi.y)*tanhf(zg.y);
        cn.z = sigf(zf.z)*c1.z + sigf(zi.z)*tanhf(zg.z);
        cn.w = sigf(zf.w)*c1.w + sigf(zi.w)*tanhf(zg.w);
        hn.x = sigf(zo.x)*tanhf(cn.x);
        hn.y = sigf(zo.y)*tanhf(cn.y);
        hn.z = sigf(zo.z)*tanhf(cn.z);
        hn.w = sigf(zo.w)*tanhf(cn.w);
        float om = 1.f - s;
        *(float4*)(g_x2 + base) = make_float4(hn.x*s, hn.y*s, hn.z*s, hn.w*s);
        *(float4*)(g_h1 + base) = make_float4(hn.x*om, hn.y*om, hn.z*om, hn.w*om);
        *(float4*)(g_c1 + base) = make_float4(cn.x*om, cn.y*om, cn.z*om, cn.w*om);
    }
}

__device__ void gate2out_item(int t, int g, float* __restrict__ out,
                              const float* __restrict__ b2, bool fin)
{
    bool upd = g_flagbuf[t & 1] > 0.5f;
    int b0 = g*8;
    int h = threadIdx.x * 4;
    for (int b = b0; b < b0+8; b++) {
        int base = b*HH + h;
        float4 hv, cv;
        if (upd) {
            float4 zi = *(const float4*)(b2 + h);
            float4 zf = *(const float4*)(b2 + HH + h);
            float4 zg = *(const float4*)(b2 + 2*HH + h);
            float4 zo = *(const float4*)(b2 + 3*HH + h);
            #pragma unroll
            for (int c = 0; c < 8; c++) {
                const float* pp = g_z2bP + (size_t)c*BB*Z4 + (size_t)b*Z4;
                zi = f4add(zi, *(const float4*)(pp + h));
                zf = f4add(zf, *(const float4*)(pp + HH + h));
                zg = f4add(zg, *(const float4*)(pp + 2*HH + h));
                zo = f4add(zo, *(const float4*)(pp + 3*HH + h));
            }
            float4 c2 = *(const float4*)(g_c2 + base);
            cv.x = sigf(zf.x)*c2.x + sigf(zi.x)*tanhf(zg.x);
            cv.y = sigf(zf.y)*c2.y + sigf(zi.y)*tanhf(zg.y);
            cv.z = sigf(zf.z)*c2.z + sigf(zi.z)*tanhf(zg.z);
            cv.w = sigf(zf.w)*c2.w + sigf(zi.w)*tanhf(zg.w);
            hv.x = sigf(zo.x)*tanhf(cv.x);
            hv.y = sigf(zo.y)*tanhf(cv.y);
            hv.z = sigf(zo.z)*tanhf(cv.z);
            hv.w = sigf(zo.w)*tanhf(cv.w);
            *(float4*)(g_c2 + base) = cv;
            *(float4*)(g_h2 + base) = hv;
        } else {
            hv = *(const float4*)(g_h2 + base);
            cv = *(const float4*)(g_c2 + base);
        }
        *(float4*)(out + (size_t)b*SL*HH + (size_t)t*HH + h) = hv;
        if (fin) {
            size_t off = (size_t)BB*SL*HH;
            *(float4*)(out + off + base) = hv;
            *(float4*)(out + off + (size_t)BB*HH + base) = cv;
        }
    }
}

__device__ void sdot_item(int t, int k, float* __restrict__ out)
{
    int warp = threadIdx.x >> 5, lane = threadIdx.x & 31;
    int base = k*32 + warp*4;
    for (int bi = 0; bi < 4; bi++) {
        int b = base + bi;
        const float* hp = g_h1 + (size_t)b*HH;
        float p = 0.f;
        for (int j = lane; j < HH; j += 32) p += hp[j] * g_u[j];
        #pragma unroll
        for (int o = 16; o; o >>= 1) p += __shfl_xor_sync(0xffffffffu, p, o);
        if (lane == 0) {
            float sv = (p + g_d[(size_t)t*BB + b] > 0.f) ? 1.f : 0.f;
            g_s[b] = sv;
            if (b == 0) {
                g_flagbuf[t & 1] = sv;
                out[(size_t)BB*SL*HH + 2*(size_t)BB*HH + t] = sv;
            }
        }
    }
}

// ---------------- persistent recurrent-loop kernel ----------------
__global__ void __launch_bounds__(256, 1) k_loop(
    const float* __restrict__ Wmh1, const float* __restrict__ Whh1,
    const float* __restrict__ Wmx2, const float* __restrict__ Wmh2,
    const float* __restrict__ Wih2, const float* __restrict__ Whh2,
    const float* __restrict__ b2, float* __restrict__ out)
{
    __shared__ __align__(16) float As[16*132];
    __shared__ __align__(16) float Ws[16*132];
    const int bid = blockIdx.x;
    const unsigned G = gridDim.x;

    for (int t = 0; t < SL; t++) {
        const float* pre_mx = g_pmx + (size_t)t*BB*HH;
        const float* pre_ih = g_pih + (size_t)t*BB*Z4;

        // Phase A: m1 partials (128) | gate2out(t-1) (16) | sdot (4)
        for (int it = bid; it < 148; it += G) {
            if (it < 128) {
                int nt = it >> 4, kc = it & 15;
                dg128<0>(g_h1, HH, Wmh1, HH, g_m1P + (size_t)kc*BB*HH, HH,
                         0, nt*128, kc*64, 4, nullptr, As, Ws);
            } else if (it < 144) {
                if (t > 0) gate2out_item(t-1, it-128, out, b2, false);
            } else
                sdot_item(t, it-144, out);
        }
        gsync(G);

        // Phase A2: m1 = pre_mx * sum(partials)
        for (int it = bid; it < 16; it += G) fin_m1(it, pre_mx);
        gsync(G);

        float flag = g_flagbuf[t & 1];
        int nB = (flag > 0.5f) ? 384 : 256;

        // Phase B: z1 partials (256) | t2 partials (128, if flag)
        for (int it = bid; it < nB; it += G) {
            if (it < 256) {
                int nt = it >> 3, kc = it & 7;
                dg128<0>(g_m1, HH, Whh1, HH, g_z1P + (size_t)kc*BB*Z4, Z4,
                         0, nt*128, kc*128, 8, nullptr, As, Ws);
            } else {
                int j = it - 256, nt = j >> 4, kc = j & 15;
                dg128<0>(g_h2, HH, Wmh2, HH, g_t2P + (size_t)kc*BB*HH, HH,
                         0, nt*128, kc*64, 4, nullptr, As, Ws);
            }
        }
        gsync(G);

        // Phase C: gate1
        for (int it = bid; it < 16; it += G) gate1_item(it, pre_ih);
        gsync(G);

        if (flag > 0.5f) {
            // Phase D: z2a partials (256) | m2x partials (128)
            for (int it = bid; it < 384; it += G) {
                if (it < 256) {
                    int nt = it >> 3, kc = it & 7;
                    dg128<0>(g_x2, HH, Wih2, HH, g_z2aP + (size_t)kc*BB*Z4, Z4,
                             0, nt*128, kc*128, 8, nullptr, As, Ws);
                } else {
                    int j = it - 256, nt = j >> 4, kc = j & 15;
                    dg128<0>(g_x2, HH, Wmx2, HH, g_m2xP + (size_t)kc*BB*HH, HH,
                             0, nt*128, kc*64, 4, nullptr, As, Ws);
                }
            }
            gsync(G);
            // Phase D2: m2 = sum(m2xP) * sum(t2P)
            for (int it = bid; it < 16; it += G) fin_m2(it);
            gsync(G);
            // Phase E: z2bP[kc] = m2@Whh2^T partial + z2aP[kc]
            for (int it = bid; it < 256; it += G) {
                int nt = it >> 3, kc = it & 7;
                dg128<2>(g_m2, HH, Whh2, HH, g_z2bP + (size_t)kc*BB*Z4, Z4,
                         0, nt*128, kc*128, 8, g_z2aP + (size_t)kc*BB*Z4, As, Ws);
            }
            gsync(G);
        }
    }

    // final step outputs + final states
    for (int it = bid; it < 16; it += (int)G)
        gate2out_item(SL-1, it, out, b2, true);
}

// ---------------- host ----------------
extern "C" void kernel_launch(void* const* d_in, const int* in_sizes, int n_in,
                              void* d_out, int out_size)
{
    const int*   enc  = (const int*)  d_in[0];
    const int*   encx = (const int*)  d_in[1];
    const float* wemb = (const float*)d_in[2];
    const float* xemb = (const float*)d_in[3];
    const float* Wsi  = (const float*)d_in[4];
    const float* Wsh  = (const float*)d_in[5];
    const float* b_bd = (const float*)d_in[6];
    const float* vs   = (const float*)d_in[7];
    const float* Wmx1 = (const float*)d_in[8];
    const float* Wmh1 = (const float*)d_in[9];
    const float* Wih1 = (const float*)d_in[10];
    const float* Whh1 = (const float*)d_in[11];
    const float* b1   = (const float*)d_in[12];
    const float* Wmx2 = (const float*)d_in[13];
    const float* Wmh2 = (const float*)d_in[14];
    const float* Wih2 = (const float*)d_in[15];
    const float* Whh2 = (const float*)d_in[16];
    const float* b2   = (const float*)d_in[17];
    float* out = (float*)d_out;

    float *pX, *pmx, *pih, *ph1, *pc1, *ph2, *pc2;
    cudaGetSymbolAddress((void**)&pX,  g_X);
    cudaGetSymbolAddress((void**)&pmx, g_pmx);
    cudaGetSymbolAddress((void**)&pih, g_pih);
    cudaGetSymbolAddress((void**)&ph1, g_h1);
    cudaGetSymbolAddress((void**)&pc1, g_c1);
    cudaGetSymbolAddress((void**)&ph2, g_h2);
    cudaGetSymbolAddress((void**)&pc2, g_c2);

    cudaMemsetAsync(ph1, 0, (size_t)BB*HH*sizeof(float));
    cudaMemsetAsync(pc1, 0, (size_t)BB*HH*sizeof(float));
    cudaMemsetAsync(ph2, 0, (size_t)BB*HH*sizeof(float));
    cudaMemsetAsync(pc2, 0, (size_t)BB*HH*sizeof(float));

    // precompute
    k_prep<<<FT + HH + 1, 256>>>(vs, Wsi, Wsh, b_bd);
    k_embed<<<NT, 128>>>(enc, encx, wemb, xemb);
    gemmP<0><<<dim3(HH/128, NT/128), 256>>>(pX, FT, Wmx1, pmx, HH, FT, nullptr);
    gemmP<1><<<dim3(Z4/128, NT/128), 256>>>(pX, FT, Wih1, pih, Z4, FT, b1);

    // recurrent loop: one persistent kernel
    k_loop<<<GCTA, 256>>>(Wmh1, Whh1, Wmx2, Wmh2, Wih2, Whh2, b2, out);
}

// round 11
// speedup vs baseline: 1.5327x; 1.2630x over previous
#include <cuda_runtime.h>
#include <math.h>

#define SL 512
#define BB 128
#define HH 1024
#define FT 576
#define MD 512
#define Z4 4096
#define NT (SL*BB)
#define G2 296        // persistent grid: 2 CTAs/SM x 148 SMs, guaranteed by launch_bounds(256,2)

typedef unsigned long long u64t;

// ---------------- static device scratch ----------------
static __device__ __align__(16) float g_X  [(size_t)NT*FT];
static __device__ __align__(16) float g_pmx[(size_t)NT*HH];   // X@Wmx1^T
static __device__ __align__(16) float g_pih[(size_t)NT*Z4];   // X@Wih1^T + b1
static __device__ __align__(16) float g_d  [(size_t)NT];      // (X@Wsi^T+b_bd)·vs
static __device__ __align__(16) float g_w  [FT];
static __device__ __align__(16) float g_u  [HH];
static __device__ float g_c0[1];
static __device__ __align__(16) float g_h1[BB*HH], g_c1[BB*HH], g_h2[BB*HH], g_c2[BB*HH];
static __device__ __align__(16) float g_m1[BB*HH], g_x2[BB*HH], g_m2[BB*HH];
static __device__ __align__(16) float g_m1P [16*(size_t)BB*HH];
static __device__ __align__(16) float g_t2P [16*(size_t)BB*HH];
static __device__ __align__(16) float g_m2xP[16*(size_t)BB*HH];
static __device__ __align__(16) float g_z1P [8*(size_t)BB*Z4];
static __device__ __align__(16) float g_z2aP[8*(size_t)BB*Z4];
static __device__ __align__(16) float g_z2bP[8*(size_t)BB*Z4];
static __device__ float g_s[BB];
static __device__ float g_flagbuf[2];

static __device__ unsigned g_bar_count = 0;
static __device__ volatile unsigned g_bar_gen = 0;

__device__ __forceinline__ float sigf(float x) { return 1.0f / (1.0f + expf(-x)); }

__device__ __forceinline__ u64t pk2(float lo, float hi) {
    u64t r; asm("mov.b64 %0, {%1, %2};" : "=l"(r) : "f"(lo), "f"(hi)); return r;
}
__device__ __forceinline__ u64t dup2(float v) {
    u64t r; asm("mov.b64 %0, {%1, %1};" : "=l"(r) : "f"(v)); return r;
}
__device__ __forceinline__ void fma2(u64t& d, u64t a, u64t b) {
    asm("fma.rn.f32x2 %0, %1, %2, %0;" : "+l"(d) : "l"(a), "l"(b));
}
__device__ __forceinline__ void upk2(u64t v, float& lo, float& hi) {
    asm("mov.b64 {%0, %1}, %2;" : "=f"(lo), "=f"(hi) : "l"(v));
}

__device__ __forceinline__ void gsync(unsigned nb)
{
    __syncthreads();
    if (threadIdx.x == 0) {
        __threadfence();
        unsigned gen = g_bar_gen;
        if (atomicAdd(&g_bar_count, 1u) == nb - 1u) {
            g_bar_count = 0;
            __threadfence();
            g_bar_gen = gen + 1u;
        } else {
            while (g_bar_gen == gen) __nanosleep(64);
        }
        __threadfence();
    }
    __syncthreads();
}

// ================= precompute GEMM tile (128x128, unchanged arithmetic from R7) =================
template<int EPI>
__device__ __noinline__ void dg128(
    const float* __restrict__ A, int lda,
    const float* __restrict__ W, int ldw,
    float* __restrict__ C, int ldc,
    int row0, int col0, int k0, int niter,
    const float* __restrict__ ex,
    float* __restrict__ As, float* __restrict__ Ws)
{
    const int tid = threadIdx.x;
    const int lm = tid >> 1;
    const int kq = (tid & 1) << 3;
    const float* Ag = A + (size_t)(row0 + lm)*lda + k0 + kq;
    const float* Wg = W + (size_t)(col0 + lm)*ldw + k0 + kq;
    const int m0 = (tid >> 4) << 3;
    const int n0 = (tid & 15) << 3;
    u64t acc[4][8];
    #pragma unroll
    for (int i = 0; i < 4; i++)
        #pragma unroll
        for (int j = 0; j < 8; j++) acc[i][j] = 0ull;

    float4 a0 = *(const float4*)Ag;
    float4 a1 = *(const float4*)(Ag + 4);
    float4 w0 = *(const float4*)Wg;
    float4 w1 = *(const float4*)(Wg + 4);

    for (int it = 0; it < niter; it++) {
        __syncthreads();
        As[(kq+0)*132+lm]=a0.x; As[(kq+1)*132+lm]=a0.y; As[(kq+2)*132+lm]=a0.z; As[(kq+3)*132+lm]=a0.w;
        As[(kq+4)*132+lm]=a1.x; As[(kq+5)*132+lm]=a1.y; As[(kq+6)*132+lm]=a1.z; As[(kq+7)*132+lm]=a1.w;
        Ws[(kq+0)*132+lm]=w0.x; Ws[(kq+1)*132+lm]=w0.y; Ws[(kq+2)*132+lm]=w0.z; Ws[(kq+3)*132+lm]=w0.w;
        Ws[(kq+4)*132+lm]=w1.x; Ws[(kq+5)*132+lm]=w1.y; Ws[(kq+6)*132+lm]=w1.z; Ws[(kq+7)*132+lm]=w1.w;
        __syncthreads();
        if (it + 1 < niter) {
            const float* An = Ag + (it+1)*16;
            const float* Wn = Wg + (it+1)*16;
            a0 = *(const float4*)An; a1 = *(const float4*)(An + 4);
            w0 = *(const float4*)Wn; w1 = *(const float4*)(Wn + 4);
        }
        #pragma unroll
        for (int kk = 0; kk < 16; kk++) {
            const float* ar = As + kk*132;
            const float* wr = Ws + kk*132;
            float4 xa0 = *(const float4*)(ar + m0);
            float4 xa1 = *(const float4*)(ar + m0 + 4);
            float4 xw0 = *(const float4*)(wr + n0);
            float4 xw1 = *(const float4*)(wr + n0 + 4);
            u64t pa[4] = { pk2(xa0.x,xa0.y), pk2(xa0.z,xa0.w),
                           pk2(xa1.x,xa1.y), pk2(xa1.z,xa1.w) };
            u64t dw[8] = { dup2(xw0.x), dup2(xw0.y), dup2(xw0.z), dup2(xw0.w),
                           dup2(xw1.x), dup2(xw1.y), dup2(xw1.z), dup2(xw1.w) };
            #pragma unroll
            for (int i = 0; i < 4; i++)
                #pragma unroll
                for (int j = 0; j < 8; j++) fma2(acc[i][j], pa[i], dw[j]);
        }
    }

    #pragma unroll
    for (int i = 0; i < 4; i++) {
        float lo[8], hi[8];
        #pragma unroll
        for (int j = 0; j < 8; j++) upk2(acc[i][j], lo[j], hi[j]);
        size_t r0 = (size_t)(row0 + m0 + 2*i) * ldc + col0 + n0;
        size_t r1 = r0 + ldc;
        float4 v0 = make_float4(lo[0],lo[1],lo[2],lo[3]);
        float4 v1 = make_float4(lo[4],lo[5],lo[6],lo[7]);
        float4 u0 = make_float4(hi[0],hi[1],hi[2],hi[3]);
        float4 u1 = make_float4(hi[4],hi[5],hi[6],hi[7]);
        if (EPI == 1) {
            float4 b0 = *(const float4*)(ex + col0 + n0);
            float4 b1 = *(const float4*)(ex + col0 + n0 + 4);
            v0.x+=b0.x; v0.y+=b0.y; v0.z+=b0.z; v0.w+=b0.w;
            v1.x+=b1.x; v1.y+=b1.y; v1.z+=b1.z; v1.w+=b1.w;
            u0.x+=b0.x; u0.y+=b0.y; u0.z+=b0.z; u0.w+=b0.w;
            u1.x+=b1.x; u1.y+=b1.y; u1.z+=b1.z; u1.w+=b1.w;
        }
        *(float4*)(C + r0)     = v0;
        *(float4*)(C + r0 + 4) = v1;
        *(float4*)(C + r1)     = u0;
        *(float4*)(C + r1 + 4) = u1;
    }
}

template<int EPI>
__global__ void __launch_bounds__(256, 2) gemmP(
    const float* __restrict__ A, int lda, const float* __restrict__ W,
    float* __restrict__ C, int N, int K, const float* __restrict__ bias)
{
    __shared__ __align__(16) float As[16*132];
    __shared__ __align__(16) float Ws[16*132];
    dg128<EPI>(A, lda, W, K, C, N, blockIdx.y*128, blockIdx.x*128, 0, K/16, bias, As, Ws);
}

// ================= loop GEMM tile: 128 rows x 64 cols =================
// Per-element K-summation order identical to R7's dg128 (N-split is rounding-neutral).
template<int EPI>
__device__ __noinline__ void dgL(
    const float* __restrict__ A, int lda,
    const float* __restrict__ W, int ldw,
    float* __restrict__ C, int ldc,
    int col0, int k0, int niter,
    const float* __restrict__ ex,
    float* __restrict__ As, float* __restrict__ Ws)
{
    const int tid = threadIdx.x;
    const int lmA = tid >> 1, kqA = (tid & 1) << 3;   // A: 128 rows x 16 k
    const int lmW = tid >> 2, kqW = (tid & 3) << 2;   // W: 64 rows x 16 k
    const float* Ag = A + (size_t)lmA*lda + k0 + kqA;
    const float* Wg = W + (size_t)(col0 + lmW)*ldw + k0 + kqW;
    const int m0 = (tid >> 4) << 3;   // 16 groups x 8 rows
    const int n0 = (tid & 15) << 2;   // 16 groups x 4 cols
    u64t acc[4][4];
    #pragma unroll
    for (int i = 0; i < 4; i++)
        #pragma unroll
        for (int j = 0; j < 4; j++) acc[i][j] = 0ull;

    float4 a0 = *(const float4*)Ag;
    float4 a1 = *(const float4*)(Ag + 4);
    float4 w0 = *(const float4*)Wg;

    for (int it = 0; it < niter; it++) {
        __syncthreads();
        As[(kqA+0)*132+lmA]=a0.x; As[(kqA+1)*132+lmA]=a0.y; As[(kqA+2)*132+lmA]=a0.z; As[(kqA+3)*132+lmA]=a0.w;
        As[(kqA+4)*132+lmA]=a1.x; As[(kqA+5)*132+lmA]=a1.y; As[(kqA+6)*132+lmA]=a1.z; As[(kqA+7)*132+lmA]=a1.w;
        Ws[(kqW+0)*68+lmW]=w0.x;  Ws[(kqW+1)*68+lmW]=w0.y;  Ws[(kqW+2)*68+lmW]=w0.z;  Ws[(kqW+3)*68+lmW]=w0.w;
        __syncthreads();
        if (it + 1 < niter) {
            const float* An = Ag + (it+1)*16;
            a0 = *(const float4*)An; a1 = *(const float4*)(An + 4);
            w0 = *(const float4*)(Wg + (it+1)*16);
        }
        #pragma unroll
        for (int kk = 0; kk < 16; kk++) {
            const float* ar = As + kk*132 + m0;
            float4 xa0 = *(const float4*)ar;
            float4 xa1 = *(const float4*)(ar + 4);
            float4 xw  = *(const float4*)(Ws + kk*68 + n0);
            u64t pa[4] = { pk2(xa0.x,xa0.y), pk2(xa0.z,xa0.w),
                           pk2(xa1.x,xa1.y), pk2(xa1.z,xa1.w) };
            u64t dw[4] = { dup2(xw.x), dup2(xw.y), dup2(xw.z), dup2(xw.w) };
            #pragma unroll
            for (int i = 0; i < 4; i++)
                #pragma unroll
                for (int j = 0; j < 4; j++) fma2(acc[i][j], pa[i], dw[j]);
        }
    }

    #pragma unroll
    for (int i = 0; i < 4; i++) {
        float lo[4], hi[4];
        #pragma unroll
        for (int j = 0; j < 4; j++) upk2(acc[i][j], lo[j], hi[j]);
        size_t r0 = (size_t)(m0 + 2*i) * ldc + col0 + n0;
        size_t r1 = r0 + ldc;
        float4 v = make_float4(lo[0],lo[1],lo[2],lo[3]);
        float4 u = make_float4(hi[0],hi[1],hi[2],hi[3]);
        if (EPI == 2) {
            float4 e0 = *(const float4*)(ex + r0);
            float4 e1 = *(const float4*)(ex + r1);
            v.x+=e0.x; v.y+=e0.y; v.z+=e0.z; v.w+=e0.w;
            u.x+=e1.x; u.y+=e1.y; u.z+=e1.z; u.w+=e1.w;
        }
        *(float4*)(C + r0) = v;
        *(float4*)(C + r1) = u;
    }
}

// ---------------- prep + embed (unchanged) ----------------
__global__ void k_prep(const float* __restrict__ vs, const float* __restrict__ Wsi,
                       const float* __restrict__ Wsh, const float* __restrict__ b_bd)
{
    int i = blockIdx.x;
    __shared__ float red[256];
    float acc = 0.f;
    if (i < FT) {
        for (int j = threadIdx.x; j < MD; j += 256) acc += vs[j] * Wsi[(size_t)j*FT + i];
    } else if (i < FT + HH) {
        int h = i - FT;
        for (int j = threadIdx.x; j < MD; j += 256) acc += vs[j] * Wsh[(size_t)j*HH + h];
    } else {
        for (int j = threadIdx.x; j < MD; j += 256) acc += vs[j] * b_bd[j];
    }
    red[threadIdx.x] = acc; __syncthreads();
    for (int off = 128; off; off >>= 1) {
        if (threadIdx.x < off) red[threadIdx.x] += red[threadIdx.x + off];
        __syncthreads();
    }
    if (threadIdx.x == 0) {
        if (i < FT) g_w[i] = red[0];
        else if (i < FT + HH) g_u[i - FT] = red[0];
        else g_c0[0] = red[0];
    }
}

__global__ void k_embed(const int* __restrict__ enc, const int* __restrict__ encx,
                        const float* __restrict__ wemb, const float* __restrict__ xemb)
{
    int n = blockIdx.x;
    int t = n >> 7;
    int b = n & 127;
    int w = enc [b*SL + t];
    int e = encx[b*SL + t];
    float4* dst = (float4*)(g_X + (size_t)n*FT);
    const float4* ws = (const float4*)(wemb + (size_t)w*512);
    const float4* xs = (const float4*)(xemb + (size_t)e*64);
    const float4* w4 = (const float4*)g_w;
    float dot = 0.f;
    for (int i = threadIdx.x; i < 128; i += 128) {
        float4 v = ws[i]; dst[i] = v;
        float4 c = w4[i];
        dot += v.x*c.x + v.y*c.y + v.z*c.z + v.w*c.w;
    }
    for (int i = threadIdx.x; i < 16; i += 128) {
        float4 v = xs[i]; dst[128 + i] = v;
        float4 c = w4[128 + i];
        dot += v.x*c.x + v.y*c.y + v.z*c.z + v.w*c.w;
    }
    __shared__ float red[128];
    red[threadIdx.x] = dot; __syncthreads();
    for (int off = 64; off; off >>= 1) {
        if (threadIdx.x < off) red[threadIdx.x] += red[threadIdx.x + off];
        __syncthreads();
    }
    if (threadIdx.x == 0) g_d[n] = red[0] + g_c0[0];
}

// ---------------- elementwise items (per-batch arithmetic identical to R7) ----------------
__device__ __forceinline__ float4 f4add(float4 a, float4 b) {
    return make_float4(a.x+b.x, a.y+b.y, a.z+b.z, a.w+b.w);
}

__device__ void fin_m1_b(int b, const float* __restrict__ pre_mx)
{
    const float4* P = (const float4*)g_m1P;
    int idx = b*256 + threadIdx.x;
    float4 s = make_float4(0.f,0.f,0.f,0.f);
    #pragma unroll
    for (int c = 0; c < 16; c++) s = f4add(s, P[(size_t)c*32768 + idx]);
    float4 m = ((const float4*)pre_mx)[idx];
    ((float4*)g_m1)[idx] = make_float4(s.x*m.x, s.y*m.y, s.z*m.z, s.w*m.w);
}

__device__ void fin_m2_b(int b)
{
    const float4* P = (const float4*)g_m2xP;
    const float4* T = (const float4*)g_t2P;
    int idx = b*256 + threadIdx.x;
    float4 s = make_float4(0.f,0.f,0.f,0.f);
    float4 u = make_float4(0.f,0.f,0.f,0.f);
    #pragma unroll
    for (int c = 0; c < 16; c++) {
        s = f4add(s, P[(size_t)c*32768 + idx]);
        u = f4add(u, T[(size_t)c*32768 + idx]);
    }
    ((float4*)g_m2)[idx] = make_float4(s.x*u.x, s.y*u.y, s.z*u.z, s.w*u.w);
}

__device__ void gate1_b(int b, const float* __restrict__ pre_ih)
{
    float s = g_s[b];
    int h = threadIdx.x * 4;
    const float* pz = pre_ih + (size_t)b*Z4;
    float4 zi = *(const float4*)(pz + h);
    float4 zf = *(const float4*)(pz + HH + h);
    float4 zg = *(const float4*)(pz + 2*HH + h);
    float4 zo = *(const float4*)(pz + 3*HH + h);
    #pragma unroll
    for (int c = 0; c < 8; c++) {
        const float* pp = g_z1P + (size_t)c*BB*Z4 + (size_t)b*Z4;
        zi = f4add(zi, *(const float4*)(pp + h));
        zf = f4add(zf, *(const float4*)(pp + HH + h));
        zg = f4add(zg, *(const float4*)(pp + 2*HH + h));
        zo = f4add(zo, *(const float4*)(pp + 3*HH + h));
    }
    int base = b*HH + h;
    float4 c1 = *(const float4*)(g_c1 + base);
    float4 cn, hn;
    cn.x = sigf(zf.x)*c1.x + sigf(zi.x)*tanhf(zg.x);
    cn.y = sigf(zf.y)*c1.y + sigf(zi.y)*tanhf(zg.y);
    cn.z = sigf(zf.z)*c1.z + sigf(zi.z)*tanhf(zg.z);
    cn.w = sigf(zf.w)*c1.w + sigf(zi.w)*tanhf(zg.w);
    hn.x = sigf(zo.x)*tanhf(cn.x);
    hn.y = sigf(zo.y)*tanhf(cn.y);
    hn.z = sigf(zo.z)*tanhf(cn.z);
    hn.w = sigf(zo.w)*tanhf(cn.w);
    float om = 1.f - s;
    *(float4*)(g_x2 + base) = make_float4(hn.x*s, hn.y*s, hn.z*s, hn.w*s);
    *(float4*)(g_h1 + base) = make_float4(hn.x*om, hn.y*om, hn.z*om, hn.w*om);
    *(float4*)(g_c1 + base) = make_float4(cn.x*om, cn.y*om, cn.z*om, cn.w*om);
}

__device__ void gate2out4(int t, int g, float* __restrict__ out,
                          const float* __restrict__ b2, bool fin)
{
    bool upd = g_flagbuf[t & 1] > 0.5f;
    int b0 = g*4;
    int h = threadIdx.x * 4;
    for (int b = b0; b < b0+4; b++) {
        int base = b*HH + h;
        float4 hv, cv;
        if (upd) {
            float4 zi = *(const float4*)(b2 + h);
            float4 zf = *(const float4*)(b2 + HH + h);
            float4 zg = *(const float4*)(b2 + 2*HH + h);
            float4 zo = *(const float4*)(b2 + 3*HH + h);
            #pragma unroll
            for (int c = 0; c < 8; c++) {
                const float* pp = g_z2bP + (size_t)c*BB*Z4 + (size_t)b*Z4;
                zi = f4add(zi, *(const float4*)(pp + h));
                zf = f4add(zf, *(const float4*)(pp + HH + h));
                zg = f4add(zg, *(const float4*)(pp + 2*HH + h));
                zo = f4add(zo, *(const float4*)(pp + 3*HH + h));
            }
            float4 c2 = *(const float4*)(g_c2 + base);
            cv.x = sigf(zf.x)*c2.x + sigf(zi.x)*tanhf(zg.x);
            cv.y = sigf(zf.y)*c2.y + sigf(zi.y)*tanhf(zg.y);
            cv.z = sigf(zf.z)*c2.z + sigf(zi.z)*tanhf(zg.z);
            cv.w = sigf(zf.w)*c2.w + sigf(zi.w)*tanhf(zg.w);
            hv.x = sigf(zo.x)*tanhf(cv.x);
            hv.y = sigf(zo.y)*tanhf(cv.y);
            hv.z = sigf(zo.z)*tanhf(cv.z);
            hv.w = sigf(zo.w)*tanhf(cv.w);
            *(float4*)(g_c2 + base) = cv;
            *(float4*)(g_h2 + base) = hv;
        } else {
            hv = *(const float4*)(g_h2 + base);
            cv = *(const float4*)(g_c2 + base);
        }
        *(float4*)(out + (size_t)b*SL*HH + (size_t)t*HH + h) = hv;
        if (fin) {
            size_t off = (size_t)BB*SL*HH;
            *(float4*)(out + off + base) = hv;
            *(float4*)(out + off + (size_t)BB*HH + base) = cv;
        }
    }
}

__device__ void sdot16(int t, int k, float* __restrict__ out)
{
    int warp = threadIdx.x >> 5, lane = threadIdx.x & 31;
    int base = k*16 + warp*2;
    for (int bi = 0; bi < 2; bi++) {
        int b = base + bi;
        const float* hp = g_h1 + (size_t)b*HH;
        float p = 0.f;
        for (int j = lane; j < HH; j += 32) p += hp[j] * g_u[j];
        #pragma unroll
        for (int o = 16; o; o >>= 1) p += __shfl_xor_sync(0xffffffffu, p, o);
        if (lane == 0) {
            float sv = (p + g_d[(size_t)t*BB + b] > 0.f) ? 1.f : 0.f;
            g_s[b] = sv;
            if (b == 0) {
                g_flagbuf[t & 1] = sv;
                out[(size_t)BB*SL*HH + 2*(size_t)BB*HH + t] = sv;
            }
        }
    }
}

// ---------------- persistent recurrent-loop kernel (2 CTAs/SM) ----------------
__global__ void __launch_bounds__(256, 2) k_loop(
    const float* __restrict__ Wmh1, const float* __restrict__ Whh1,
    const float* __restrict__ Wmx2, const float* __restrict__ Wmh2,
    const float* __restrict__ Wih2, const float* __restrict__ Whh2,
    const float* __restrict__ b2, float* __restrict__ out)
{
    __shared__ __align__(16) float As[16*132];
    __shared__ __align__(16) float Ws[16*68];
    const int bid = blockIdx.x;
    const unsigned G = gridDim.x;

    for (int t = 0; t < SL; t++) {
        const float* pre_mx = g_pmx + (size_t)t*BB*HH;
        const float* pre_ih = g_pih + (size_t)t*BB*Z4;

        // Phase A (296 items == G): m1 partials (256) | gate2out(t-1) (32) | sdot (8)
        for (int it = bid; it < 296; it += G) {
            if (it < 256) {
                int nt = it >> 4, kc = it & 15;
                dgL<0>(g_h1, HH, Wmh1, HH, g_m1P + (size_t)kc*BB*HH, HH,
                       nt*64, kc*64, 4, nullptr, As, Ws);
            } else if (it < 288) {
                if (t > 0) gate2out4(t-1, it-256, out, b2, false);
            } else
                sdot16(t, it-288, out);
        }
        gsync(G);

        // Phase A2: m1 = pre_mx * sum(partials)  (128 items)
        for (int it = bid; it < 128; it += G) fin_m1_b(it, pre_mx);
        gsync(G);

        float flag = g_flagbuf[t & 1];
        int nB = (flag > 0.5f) ? 768 : 512;

        // Phase B: z1 partials (512) | t2 partials (256, flag)
        for (int it = bid; it < nB; it += G) {
            if (it < 512) {
                int nt = it >> 3, kc = it & 7;
                dgL<0>(g_m1, HH, Whh1, HH, g_z1P + (size_t)kc*BB*Z4, Z4,
                       nt*64, kc*128, 8, nullptr, As, Ws);
            } else {
                int j = it - 512, nt = j >> 4, kc = j & 15;
                dgL<0>(g_h2, HH, Wmh2, HH, g_t2P + (size_t)kc*BB*HH, HH,
                       nt*64, kc*64, 4, nullptr, As, Ws);
            }
        }
        gsync(G);

        // Phase C: gate1 (128 items)
        for (int it = bid; it < 128; it += G) gate1_b(it, pre_ih);
        gsync(G);

        if (flag > 0.5f) {
            // Phase D: z2a partials (512) | m2x partials (256)
            for (int it = bid; it < 768; it += G) {
                if (it < 512) {
                    int nt = it >> 3, kc = it & 7;
                    dgL<0>(g_x2, HH, Wih2, HH, g_z2aP + (size_t)kc*BB*Z4, Z4,
                           nt*64, kc*128, 8, nullptr, As, Ws);
                } else {
                    int j = it - 512, nt = j >> 4, kc = j & 15;
                    dgL<0>(g_x2, HH, Wmx2, HH, g_m2xP + (size_t)kc*BB*HH, HH,
                           nt*64, kc*64, 4, nullptr, As, Ws);
                }
            }
            gsync(G);
            // Phase D2: m2 = sum(m2xP) * sum(t2P)  (128 items)
            for (int it = bid; it < 128; it += G) fin_m2_b(it);
            gsync(G);
            // Phase E: z2bP[kc] = m2@Whh2^T partial + z2aP[kc]  (512 items)
            for (int it = bid; it < 512; it += G) {
                int nt = it >> 3, kc = it & 7;
                dgL<2>(g_m2, HH, Whh2, HH, g_z2bP + (size_t)kc*BB*Z4, Z4,
                       nt*64, kc*128, 8, g_z2aP + (size_t)kc*BB*Z4, As, Ws);
            }
            gsync(G);
        }
    }

    // final step outputs + final states
    for (int it = bid; it < 32; it += (int)G)
        gate2out4(SL-1, it, out, b2, true);
}

// ---------------- host ----------------
extern "C" void kernel_launch(void* const* d_in, const int* in_sizes, int n_in,
                              void* d_out, int out_size)
{
    const int*   enc  = (const int*)  d_in[0];
    const int*   encx = (const int*)  d_in[1];
    const float* wemb = (const float*)d_in[2];
    const float* xemb = (const float*)d_in[3];
    const float* Wsi  = (const float*)d_in[4];
    const float* Wsh  = (const float*)d_in[5];
    const float* b_bd = (const float*)d_in[6];
    const float* vs   = (const float*)d_in[7];
    const float* Wmx1 = (const float*)d_in[8];
    const float* Wmh1 = (const float*)d_in[9];
    const float* Wih1 = (const float*)d_in[10];
    const float* Whh1 = (const float*)d_in[11];
    const float* b1   = (const float*)d_in[12];
    const float* Wmx2 = (const float*)d_in[13];
    const float* Wmh2 = (const float*)d_in[14];
    const float* Wih2 = (const float*)d_in[15];
    const float* Whh2 = (const float*)d_in[16];
    const float* b2   = (const float*)d_in[17];
    float* out = (float*)d_out;

    float *pX, *pmx, *pih, *ph1, *pc1, *ph2, *pc2;
    cudaGetSymbolAddress((void**)&pX,  g_X);
    cudaGetSymbolAddress((void**)&pmx, g_pmx);
    cudaGetSymbolAddress((void**)&pih, g_pih);
    cudaGetSymbolAddress((void**)&ph1, g_h1);
    cudaGetSymbolAddress((void**)&pc1, g_c1);
    cudaGetSymbolAddress((void**)&ph2, g_h2);
    cudaGetSymbolAddress((void**)&pc2, g_c2);

    cudaMemsetAsync(ph1, 0, (size_t)BB*HH*sizeof(float));
    cudaMemsetAsync(pc1, 0, (size_t)BB*HH*sizeof(float));
    cudaMemsetAsync(ph2, 0, (size_t)BB*HH*sizeof(float));
    cudaMemsetAsync(pc2, 0, (size_t)BB*HH*sizeof(float));

    // precompute
    k_prep<<<FT + HH + 1, 256>>>(vs, Wsi, Wsh, b_bd);
    k_embed<<<NT, 128>>>(enc, encx, wemb, xemb);
    gemmP<0><<<dim3(HH/128, NT/128), 256>>>(pX, FT, Wmx1, pmx, HH, FT, nullptr);
    gemmP<1><<<dim3(Z4/128, NT/128), 256>>>(pX, FT, Wih1, pih, Z4, FT, b1);

    // recurrent loop: one persistent kernel, 2 CTAs/SM
    k_loop<<<G2, 256>>>(Wmh1, Whh1, Wmx2, Wmh2, Wih2, Whh2, b2, out);
}